// round 12
// baseline (speedup 1.0000x reference)
#include <cuda_runtime.h>
#include <math.h>

typedef unsigned long long u64;

#define NN   32768
#define EE   262144
#define FF   64
#define ZZ   10
#define NBB  8
#define LL   2
#define HH   16

#define EPSC   0.24253562503633297f
#define SQRT2C 1.4142135623730951f
#define PI_F   3.14159265358979323846f

// Scratch (device globals; allocation-free)
__device__ __align__(16) float g_sA[NN * FF];
__device__ __align__(16) float g_vA[NN * 3 * FF];
__device__ __align__(16) float g_sB[NN * FF];
__device__ __align__(16) float g_vB[NN * 3 * FF];
__device__ __align__(16) float g_aggS[NN * FF];
__device__ __align__(16) float g_aggV[NN * 3 * FF];

__device__ __forceinline__ void redAdd1(float* p, float v) {
    asm volatile("red.global.add.f32 [%0], %1;" :: "l"(p), "f"(v) : "memory");
}
__device__ __forceinline__ u64 pk2(float lo, float hi) {
    u64 r; asm("mov.b64 %0, {%1, %2};" : "=l"(r) : "f"(lo), "f"(hi)); return r;
}
__device__ __forceinline__ void upk2(u64 v, float& lo, float& hi) {
    asm("mov.b64 {%0, %1}, %2;" : "=f"(lo), "=f"(hi) : "l"(v));
}
__device__ __forceinline__ u64 fma2(u64 a, u64 b, u64 c) {
    u64 r; asm("fma.rn.f32x2 %0, %1, %2, %3;" : "=l"(r) : "l"(a), "l"(b), "l"(c)); return r;
}

// ---------------------------------------------------------------------------
// Init
// ---------------------------------------------------------------------------
__global__ void initK(const float* __restrict__ embed, const int* __restrict__ spec) {
    int i = blockIdx.x * 256 + threadIdx.x;
    if (i >= NN * FF / 4) return;
    int n = i >> 4, f4 = i & 15;
    ((float4*)g_sA)[i] = ((const float4*)embed)[spec[n] * 16 + f4];
    float4 z = make_float4(0.f, 0.f, 0.f, 0.f);
    ((float4*)g_aggS)[i] = z;
#pragma unroll
    for (int k = 0; k < 3; k++) {
        ((float4*)g_vA)[(n * 3 + k) * 16 + f4]   = z;
        ((float4*)g_aggV)[(n * 3 + k) * 16 + f4] = z;
    }
}

// ---------------------------------------------------------------------------
// Per-edge scalar staging (round-7 proven)
// ---------------------------------------------------------------------------
__device__ __forceinline__ void stageEdge(
        float (*rb)[32], float (*yv)[32], int* sS, int* rS,
        const float* __restrict__ vec,
        const int* __restrict__ snd, const int* __restrict__ rcv,
        int e, int lane) {
    sS[lane] = snd[e];
    rS[lane] = rcv[e];
    float vx = vec[e * 3 + 0], vy = vec[e * 3 + 1], vz = vec[e * 3 + 2];
    float r  = sqrtf(vx * vx + vy * vy + vz * vz + 1e-12f);
    float rc = fmaxf(r, 1e-6f);
    float env = 0.f;
    if (r < 1.f) {
        float r2 = r * r, r6 = r2 * r2 * r2;
        env = 1.f - 28.f * r6 + 48.f * r6 * r - 21.f * r6 * r2;
    }
    float scale = SQRT2C * env / rc;
    float s1, c1;
    __sincosf(PI_F * rc, &s1, &c1);
    float c2 = 2.f * c1, sp = s1, spp = 0.f;
    rb[0][lane] = s1 * scale;
#pragma unroll
    for (int n = 1; n < NBB; n++) {
        float sn = c2 * sp - spp;
        rb[n][lane] = sn * scale;
        spp = sp; sp = sn;
    }
    float iy = 1.f / r;
    yv[0][lane] = vx * iy; yv[1][lane] = vy * iy; yv[2][lane] = vz * iy;
}

// ---------------------------------------------------------------------------
// Edge kernel (round-7 proven)
// ---------------------------------------------------------------------------
template <bool FIRST>
__global__ void __launch_bounds__(256) edgeK(
                      const float* __restrict__ vec,
                      const float* __restrict__ WrL,
                      const int*   __restrict__ snd,
                      const int*   __restrict__ rcv,
                      const float* __restrict__ sIn,
                      const float* __restrict__ vIn) {
    const int NP = FIRST ? 2 : 5;
    __shared__ float rbS[2][NBB][32];
    __shared__ float yS[2][3][32];
    __shared__ int   sndS[2][32];
    __shared__ int   rcvS[2][32];

    int t = threadIdx.x, f = t & 63, el = t >> 6;

    float wreg[NBB][FIRST ? 2 : 5];
#pragma unroll
    for (int n = 0; n < NBB; n++)
#pragma unroll
        for (int pi = 0; pi < NP; pi++) {
            int p = FIRST ? pi * 2 : pi;
            wreg[n][pi] = WrL[n * 320 + p * 64 + f];
        }

    int base = blockIdx.x * 128;
    if (t < 32)
        stageEdge(rbS[0], yS[0], sndS[0], rcvS[0], vec, snd, rcv, base + t, t);
    __syncthreads();

#pragma unroll
    for (int s = 0; s < 4; s++) {
        int buf = s & 1;
        if (s < 3 && t < 32)
            stageEdge(rbS[buf ^ 1], yS[buf ^ 1], sndS[buf ^ 1], rcvS[buf ^ 1],
                      vec, snd, rcv, base + (s + 1) * 32 + t, t);

        int e0 = el * 8;
#pragma unroll 2
        for (int le = 0; le < 8; le++) {
            int li = e0 + le;
            int s_ = sndS[buf][li];
            int r_ = rcvS[buf][li];

            float w[5];
#pragma unroll
            for (int pi = 0; pi < NP; pi++) w[pi] = 0.f;
#pragma unroll
            for (int n = 0; n < NBB; n++) {
                float rn = rbS[buf][n][li];
#pragma unroll
                for (int pi = 0; pi < NP; pi++)
                    w[pi] = fmaf(rn, wreg[n][pi], w[pi]);
            }

            float y0 = yS[buf][0][li], y1 = yS[buf][1][li], y2 = yS[buf][2][li];
            float ss = sIn[s_ * FF + f];

            float m0, m1x, m1y, m1z;
            if (FIRST) {
                m0 = w[0] * ss;
                float cc = w[1] * ss;
                m1x = cc * y0; m1y = cc * y1; m1z = cc * y2;
            } else {
                float vsx = vIn[(s_ * 3 + 0) * FF + f];
                float vsy = vIn[(s_ * 3 + 1) * FF + f];
                float vsz = vIn[(s_ * 3 + 2) * FF + f];
                float dot = vsx * y0 + vsy * y1 + vsz * y2;
                m0 = w[0] * ss + w[1] * dot;
                float cc = w[2] * ss;
                m1x = cc * y0 + w[3] * vsx + w[4] * (vsy * y2 - vsz * y1);
                m1y = cc * y1 + w[3] * vsy + w[4] * (vsz * y0 - vsx * y2);
                m1z = cc * y2 + w[3] * vsz + w[4] * (vsx * y1 - vsy * y0);
            }

            redAdd1(&g_aggS[r_ * FF + f], m0);
            redAdd1(&g_aggV[(r_ * 3 + 0) * FF + f], m1x);
            redAdd1(&g_aggV[(r_ * 3 + 1) * FF + f], m1y);
            redAdd1(&g_aggV[(r_ * 3 + 2) * FF + f], m1z);
        }
        __syncthreads();
    }
}

// ---------------------------------------------------------------------------
// Node kernel v4: f32x2 GEMMs with pre-duplicated A-operands.
// 16 nodes/block x 16 threads/node (4 channels = 2 packed pairs per thread).
// Inner loop per j: 4 LDS.64 (dup A) + 2 LDS.128 (weights = packed pairs)
// + 8 FFMA2. Layer-1 skip GEMM runs FIRST (weights from L2 as ulonglong2).
// Smem: Wb0[4096]f Wb1[4096]f | A2s u64[16*64] | A2v u64[16*192] = 64KB.
// ---------------------------------------------------------------------------
template <int LAYER>
__global__ void __launch_bounds__(256) nodeK(
                      const float* __restrict__ sOld,
                      const float* __restrict__ vOld,
                      float* __restrict__ sNew,
                      float* __restrict__ vNew,
                      const int*   __restrict__ spec,
                      const float* __restrict__ WlsL,
                      const float* __restrict__ WlvL,
                      const float* __restrict__ pwL,
                      const float* __restrict__ WpsL,
                      const float* __restrict__ WpvL,
                      const float* __restrict__ skipS,
                      const float* __restrict__ skipV,
                      const float* __restrict__ Wread0,
                      const float* __restrict__ Wr1a,
                      const float* __restrict__ Wr1b,
                      float* __restrict__ out) {
    extern __shared__ float sm[];
    float* Wb0 = sm;                     // [64][64]
    float* Wb1 = sm + 4096;              // [64][64]
    u64*   A2s = (u64*)(sm + 8192);      // [16][64]  (floats 8192..10240)
    u64*   A2v = (u64*)(sm + 10240);     // [16][3][64] (floats 10240..16384)

    int t  = threadIdx.x;
    int nl = t >> 4;
    int fi = t & 15;
    int c0 = fi * 4;
    int n  = blockIdx.x * 16 + nl;
    int z  = spec[n];

    // accumulators: final (skip-initialized on layer 1)
    u64 fsA = 0, fsB = 0, fxA = 0, fxB = 0, fyA = 0, fyB = 0, fzA = 0, fzB = 0;

    // ---- Layer 1 only: stage OLD features duplicated, skip GEMM ----
    if (LAYER > 0) {
        {
            float4 b = ((const float4*)sOld)[n * 16 + fi];
            A2s[nl * 64 + c0 + 0] = pk2(b.x, b.x);
            A2s[nl * 64 + c0 + 1] = pk2(b.y, b.y);
            A2s[nl * 64 + c0 + 2] = pk2(b.z, b.z);
            A2s[nl * 64 + c0 + 3] = pk2(b.w, b.w);
#pragma unroll
            for (int k = 0; k < 3; k++) {
                float4 v = ((const float4*)vOld)[(n * 3 + k) * 16 + fi];
                u64* d = &A2v[(nl * 3 + k) * 64 + c0];
                d[0] = pk2(v.x, v.x); d[1] = pk2(v.y, v.y);
                d[2] = pk2(v.z, v.z); d[3] = pk2(v.w, v.w);
            }
        }
        __syncthreads();
        const float* Ss = skipS + z * FF * FF;
        const float* Sv = skipV + z * FF * FF;
#pragma unroll 4
        for (int j = 0; j < FF; j++) {
            u64 as = A2s[nl * 64 + j];
            u64 ax = A2v[(nl * 3 + 0) * 64 + j];
            u64 ay = A2v[(nl * 3 + 1) * 64 + j];
            u64 az = A2v[(nl * 3 + 2) * 64 + j];
            ulonglong2 w0 = *(const ulonglong2*)&Ss[j * 64 + c0];
            ulonglong2 w1 = *(const ulonglong2*)&Sv[j * 64 + c0];
            fsA = fma2(as, w0.x, fsA); fsB = fma2(as, w0.y, fsB);
            fxA = fma2(ax, w1.x, fxA); fxB = fma2(ax, w1.y, fxB);
            fyA = fma2(ay, w1.x, fyA); fyB = fma2(ay, w1.y, fyB);
            fzA = fma2(az, w1.x, fzA); fzB = fma2(az, w1.y, fzB);
        }
        __syncthreads();
    }

    // ---- Stage agg (duplicated, *EPS) + Wls/Wlv ----
    {
        const float4* a4 = (const float4*)WlsL;
        const float4* b4 = (const float4*)WlvL;
        for (int i = t; i < 1024; i += 256) {
            ((float4*)Wb0)[i] = a4[i];
            ((float4*)Wb1)[i] = b4[i];
        }
        float4 a = ((const float4*)g_aggS)[n * 16 + fi];
        A2s[nl * 64 + c0 + 0] = pk2(a.x * EPSC, a.x * EPSC);
        A2s[nl * 64 + c0 + 1] = pk2(a.y * EPSC, a.y * EPSC);
        A2s[nl * 64 + c0 + 2] = pk2(a.z * EPSC, a.z * EPSC);
        A2s[nl * 64 + c0 + 3] = pk2(a.w * EPSC, a.w * EPSC);
#pragma unroll
        for (int k = 0; k < 3; k++) {
            float4 v = ((const float4*)g_aggV)[(n * 3 + k) * 16 + fi];
            u64* d = &A2v[(nl * 3 + k) * 64 + c0];
            d[0] = pk2(v.x * EPSC, v.x * EPSC);
            d[1] = pk2(v.y * EPSC, v.y * EPSC);
            d[2] = pk2(v.z * EPSC, v.z * EPSC);
            d[3] = pk2(v.w * EPSC, v.w * EPSC);
        }
        if (LAYER == 0) {
            float4 zz = make_float4(0.f, 0.f, 0.f, 0.f);
            ((float4*)g_aggS)[n * 16 + fi] = zz;
#pragma unroll
            for (int k = 0; k < 3; k++) ((float4*)g_aggV)[(n * 3 + k) * 16 + fi] = zz;
        }
    }
    __syncthreads();

    // ---- Phase 1: s2 = aggS@Wls, v2 = aggV@Wlv ----
    u64 s2a = 0, s2b = 0, vxa = 0, vxb = 0, vya = 0, vyb = 0, vza = 0, vzb = 0;
#pragma unroll 4
    for (int j = 0; j < FF; j++) {
        u64 as = A2s[nl * 64 + j];
        u64 ax = A2v[(nl * 3 + 0) * 64 + j];
        u64 ay = A2v[(nl * 3 + 1) * 64 + j];
        u64 az = A2v[(nl * 3 + 2) * 64 + j];
        ulonglong2 w0 = *(const ulonglong2*)&Wb0[j * 64 + c0];
        ulonglong2 w1 = *(const ulonglong2*)&Wb1[j * 64 + c0];
        s2a = fma2(as, w0.x, s2a); s2b = fma2(as, w0.y, s2b);
        vxa = fma2(ax, w1.x, vxa); vxb = fma2(ax, w1.y, vxb);
        vya = fma2(ay, w1.x, vya); vyb = fma2(ay, w1.y, vyb);
        vza = fma2(az, w1.x, vza); vzb = fma2(az, w1.y, vzb);
    }

    // ---- Product basis (scalar, per channel) ----
    float S[4], VX[4], VY[4], VZ[4];
    upk2(s2a, S[0], S[1]);  upk2(s2b, S[2], S[3]);
    upk2(vxa, VX[0], VX[1]); upk2(vxb, VX[2], VX[3]);
    upk2(vya, VY[0], VY[1]); upk2(vyb, VY[2], VY[3]);
    upk2(vza, VZ[0], VZ[1]); upk2(vzb, VZ[2], VZ[3]);

    const float* pp = pwL + z * 9 * FF;
    float4 P[9];
#pragma unroll
    for (int k = 0; k < 9; k++) P[k] = *(const float4*)&pp[k * FF + c0];

    float PS[4], PX[4], PY[4], PZ[4];
#pragma unroll
    for (int c = 0; c < 4; c++) {
        float s1 = S[c];
        float vv = VX[c] * VX[c] + VY[c] * VY[c] + VZ[c] * VZ[c];
        float s2q = s1 * s1;
        PS[c] = (&P[0].x)[c] * s1 + (&P[1].x)[c] * s2q + (&P[2].x)[c] * vv
              + (&P[3].x)[c] * s2q * s1 + (&P[4].x)[c] * s1 * vv;
        float pf = (&P[5].x)[c] + (&P[6].x)[c] * s1 + (&P[7].x)[c] * s2q + (&P[8].x)[c] * vv;
        PX[c] = pf * VX[c]; PY[c] = pf * VY[c]; PZ[c] = pf * VZ[c];
    }
    __syncthreads();

    // ---- Stage product basis (duplicated) + Wps/Wpv ----
    {
        A2s[nl * 64 + c0 + 0] = pk2(PS[0], PS[0]);
        A2s[nl * 64 + c0 + 1] = pk2(PS[1], PS[1]);
        A2s[nl * 64 + c0 + 2] = pk2(PS[2], PS[2]);
        A2s[nl * 64 + c0 + 3] = pk2(PS[3], PS[3]);
#pragma unroll
        for (int c = 0; c < 4; c++) {
            A2v[(nl * 3 + 0) * 64 + c0 + c] = pk2(PX[c], PX[c]);
            A2v[(nl * 3 + 1) * 64 + c0 + c] = pk2(PY[c], PY[c]);
            A2v[(nl * 3 + 2) * 64 + c0 + c] = pk2(PZ[c], PZ[c]);
        }
        const float4* a4 = (const float4*)WpsL;
        const float4* b4 = (const float4*)WpvL;
        for (int i = t; i < 1024; i += 256) {
            ((float4*)Wb0)[i] = a4[i];
            ((float4*)Wb1)[i] = b4[i];
        }
    }
    __syncthreads();

    // ---- Phase 2: final = product@Wp (+skip already in f accums) ----
#pragma unroll 4
    for (int j = 0; j < FF; j++) {
        u64 as = A2s[nl * 64 + j];
        u64 ax = A2v[(nl * 3 + 0) * 64 + j];
        u64 ay = A2v[(nl * 3 + 1) * 64 + j];
        u64 az = A2v[(nl * 3 + 2) * 64 + j];
        ulonglong2 w0 = *(const ulonglong2*)&Wb0[j * 64 + c0];
        ulonglong2 w1 = *(const ulonglong2*)&Wb1[j * 64 + c0];
        fsA = fma2(as, w0.x, fsA); fsB = fma2(as, w0.y, fsB);
        fxA = fma2(ax, w1.x, fxA); fxB = fma2(ax, w1.y, fxB);
        fyA = fma2(ay, w1.x, fyA); fyB = fma2(ay, w1.y, fyB);
        fzA = fma2(az, w1.x, fzA); fzB = fma2(az, w1.y, fzB);
    }

    float SN[4];
    upk2(fsA, SN[0], SN[1]); upk2(fsB, SN[2], SN[3]);

    if (LAYER < LL - 1) {
        float v0, v1, v2, v3;
        ((float4*)sNew)[n * 16 + fi] = make_float4(SN[0], SN[1], SN[2], SN[3]);
        upk2(fxA, v0, v1); upk2(fxB, v2, v3);
        ((float4*)vNew)[(n * 3 + 0) * 16 + fi] = make_float4(v0, v1, v2, v3);
        upk2(fyA, v0, v1); upk2(fyB, v2, v3);
        ((float4*)vNew)[(n * 3 + 1) * 16 + fi] = make_float4(v0, v1, v2, v3);
        upk2(fzA, v0, v1); upk2(fzB, v2, v3);
        ((float4*)vNew)[(n * 3 + 2) * 16 + fi] = make_float4(v0, v1, v2, v3);
    }

    if (LAYER == 0) {
        float4 wr = *(const float4*)&Wread0[c0];
        float part = SN[0] * wr.x + SN[1] * wr.y + SN[2] * wr.z + SN[3] * wr.w;
#pragma unroll
        for (int o = 8; o > 0; o >>= 1)
            part += __shfl_xor_sync(0xffffffffu, part, o);
        if (fi == 0) out[n * LL + 0] = part;
    } else {
        // readout MLP: stage sN rows (reuse A2s region as float[16][64])
        float* sNs = (float*)A2s;
        __syncthreads();
        *(float4*)&sNs[nl * 64 + c0] = make_float4(SN[0], SN[1], SN[2], SN[3]);
        __syncthreads();
        float a = 0.f;
#pragma unroll 8
        for (int g = 0; g < FF; g++)
            a = fmaf(sNs[nl * 64 + g], Wr1a[g * HH + fi], a);
        float sil = a / (1.f + __expf(-a));
        float part = sil * Wr1b[fi];
#pragma unroll
        for (int o = 8; o > 0; o >>= 1)
            part += __shfl_xor_sync(0xffffffffu, part, o);
        if (fi == 0) out[n * LL + (LL - 1)] = part;
    }
}

// ---------------------------------------------------------------------------
extern "C" void kernel_launch(void* const* d_in, const int* in_sizes, int n_in,
                              void* d_out, int out_size) {
    const float* vectors = (const float*)d_in[0];
    const float* embed_s = (const float*)d_in[1];
    const float* Wr      = (const float*)d_in[2];
    const float* Wls     = (const float*)d_in[3];
    const float* Wlv     = (const float*)d_in[4];
    const float* skip_s  = (const float*)d_in[5];
    const float* skip_v  = (const float*)d_in[6];
    const float* pw      = (const float*)d_in[7];
    const float* Wps     = (const float*)d_in[8];
    const float* Wpv     = (const float*)d_in[9];
    const float* Wread0  = (const float*)d_in[10];
    const float* Wr1a    = (const float*)d_in[11];
    const float* Wr1b    = (const float*)d_in[12];
    const int*   senders   = (const int*)d_in[13];
    const int*   receivers = (const int*)d_in[14];
    const int*   species   = (const int*)d_in[15];
    float* out = (float*)d_out;

    void *p_sA, *p_vA, *p_sB, *p_vB;
    cudaGetSymbolAddress(&p_sA, g_sA);
    cudaGetSymbolAddress(&p_vA, g_vA);
    cudaGetSymbolAddress(&p_sB, g_sB);
    cudaGetSymbolAddress(&p_vB, g_vB);
    float* sA = (float*)p_sA;
    float* vA = (float*)p_vA;
    float* sB = (float*)p_sB;
    float* vB = (float*)p_vB;

    const int NODE_SMEM = 16384 * 4;  // 64KB both layers
    static bool attrSet = false;
    if (!attrSet) {
        cudaFuncSetAttribute(nodeK<0>, cudaFuncAttributeMaxDynamicSharedMemorySize, NODE_SMEM);
        cudaFuncSetAttribute(nodeK<1>, cudaFuncAttributeMaxDynamicSharedMemorySize, NODE_SMEM);
        attrSet = true;
    }

    initK<<<(NN * FF / 4 + 255) / 256, 256>>>(embed_s, species);

    // ---- Layer 0 ----
    edgeK<true><<<EE / 128, 256>>>(vectors, Wr, senders, receivers, sA, vA);
    nodeK<0><<<NN / 16, 256, NODE_SMEM>>>(sA, vA, sB, vB, species,
                              Wls, Wlv, pw, Wps, Wpv,
                              skip_s, skip_v, Wread0, Wr1a, Wr1b, out);

    // ---- Layer 1 ----
    edgeK<false><<<EE / 128, 256>>>(vectors, Wr + NBB * 5 * FF, senders, receivers, sB, vB);
    nodeK<1><<<NN / 16, 256, NODE_SMEM>>>(sB, vB, sA, vA, species,
                              Wls + FF * FF, Wlv + FF * FF,
                              pw + ZZ * 9 * FF,
                              Wps + FF * FF, Wpv + FF * FF,
                              skip_s, skip_v, Wread0, Wr1a, Wr1b, out);
}